// round 10
// baseline (speedup 1.0000x reference)
#include <cuda_runtime.h>

// BlurModel: 100x100 box filter (x 1e-4), VALID, threshold >0.129 -> 1.0.
// Input  x: [8,3,1024,1024] f32 (24 images), output [8,3,925,925] f32.
//
// Fused separable filter, occupancy-tuned:
//   - 432 blocks (18 row-chunks x 24 images), 3 blocks/SM resident
//   - regs capped at 42 via __launch_bounds__(512,3): no register prefetch,
//     accumulator-advance loads are front-batched per group instead
//   - vertical sliding 100-sums in registers (2 cols/thread, 512 threads)
//   - 4 output rows per scan group, double-buffered smem (no trailing barrier)
//   - horizontal 100-sum by prefix difference, scale, threshold, store

#define IMGS   24
#define H      1024
#define W      1024
#define W2     (W / 2)
#define KS     100
#define OH     925
#define OW     925
#define RC     52           // rows per block
#define G      4            // rows per scan group
#define NG     (RC / G)     // 13 groups
#define NCHUNK 18
#define NT     512
#define NW     (NT / 32)    // 16 warps

__global__ __launch_bounds__(NT, 3) void blur_occ3(const float* __restrict__ x,
                                                   float* __restrict__ out) {
    __shared__ float sp[2][G][W];        // double-buffered row prefixes, 32 KB
    __shared__ float warpsum[2][G][NW];  // 512 B

    const int tid  = threadIdx.x;
    const int lane = tid & 31;
    const int warp = tid >> 5;
    const int img  = blockIdx.y;
    int r0 = blockIdx.x * RC;
    if (r0 > OH - RC) r0 = OH - RC;      // uniform chunks; overlap rows identical

    const float2* __restrict__ inp = (const float2*)(x + (size_t)img * H * W);

    // ---- initial vertical window: rows [r0, r0+99]
    float a0 = 0.f, a1 = 0.f;
    #pragma unroll 10
    for (int k = 0; k < KS; ++k) {
        float2 v = inp[(size_t)(r0 + k) * W2 + tid];
        a0 += v.x; a1 += v.y;
    }

    float acc0[G], acc1[G];
    acc0[0] = a0; acc1[0] = a1;
    #pragma unroll
    for (int i = 1; i < G; ++i) {
        float2 ca = inp[(size_t)(r0 + KS + i - 1) * W2 + tid];
        float2 cs = inp[(size_t)(r0 + i - 1) * W2 + tid];
        a0 += ca.x - cs.x;
        a1 += ca.y - cs.y;
        acc0[i] = a0; acc1[i] = a1;
    }

    for (int g = 0; g < NG; ++g) {
        const int rg  = r0 + G * g;
        const int buf = g & 1;

        // ---- G concurrent block prefix scans over the vertical sums
        float t[G];
        #pragma unroll
        for (int i = 0; i < G; ++i) t[i] = acc0[i] + acc1[i];

        #pragma unroll
        for (int d = 1; d < 32; d <<= 1) {
            float n[G];
            #pragma unroll
            for (int i = 0; i < G; ++i) n[i] = __shfl_up_sync(0xffffffffu, t[i], d);
            if (lane >= d) {
                #pragma unroll
                for (int i = 0; i < G; ++i) t[i] += n[i];
            }
        }
        if (lane == 31) {
            #pragma unroll
            for (int i = 0; i < G; ++i) warpsum[buf][i][warp] = t[i];
        }
        __syncthreads();

        if (warp < G) {   // warp i scans row i's 16 warp totals
            float wv = (lane < NW) ? warpsum[buf][warp][lane] : 0.f;
            #pragma unroll
            for (int d = 1; d < NW; d <<= 1) {
                float n = __shfl_up_sync(0xffffffffu, wv, d);
                if (lane >= d) wv += n;
            }
            if (lane < NW) warpsum[buf][warp][lane] = wv;
        }
        __syncthreads();

        #pragma unroll
        for (int i = 0; i < G; ++i) {
            float p1   = acc0[i] + acc1[i];
            float base = (warp ? warpsum[buf][i][warp - 1] : 0.f) + (t[i] - p1);
            sp[buf][i][2 * tid + 0] = base + acc0[i];
            sp[buf][i][2 * tid + 1] = base + p1;
        }
        __syncthreads();

        // ---- horizontal 100-sum by prefix difference, scale, threshold
        #pragma unroll
        for (int i = 0; i < G; ++i) {
            float* __restrict__ orow = out + ((size_t)img * OH + rg + i) * OW;
            #pragma unroll
            for (int j = tid; j < OW; j += NT) {
                float s = sp[buf][i][j + KS - 1] - (j ? sp[buf][i][j - 1] : 0.f);
                float o = s * 1e-4f;
                orow[j] = (o > 0.129f) ? 1.0f : o;
            }
        }
        // no trailing barrier: next group uses the other sp/warpsum buffer

        // ---- advance accumulators for rows rg+G .. rg+2G-1
        // (loads are independent -> ptxas front-batches them; single latency
        //  exposure per group, covered by the other 2 resident blocks)
        if (g + 1 < NG) {
            #pragma unroll
            for (int i = 0; i < G; ++i) {
                float2 ca = inp[(size_t)(rg + KS + G - 1 + i) * W2 + tid];
                float2 cs = inp[(size_t)(rg + G - 1 + i) * W2 + tid];
                a0 += ca.x - cs.x;
                a1 += ca.y - cs.y;
                acc0[i] = a0; acc1[i] = a1;
            }
        }
    }
}

extern "C" void kernel_launch(void* const* d_in, const int* in_sizes, int n_in,
                              void* d_out, int out_size) {
    (void)in_sizes; (void)n_in; (void)out_size;
    const float* x = (const float*)d_in[0];
    float* out     = (float*)d_out;

    dim3 grid(NCHUNK, IMGS);     // 18 x 24 = 432 blocks, 3/SM resident
    blur_occ3<<<grid, NT>>>(x, out);
}